// round 7
// baseline (speedup 1.0000x reference)
#include <cuda_runtime.h>
#include <cstdint>
#include <cstddef>

#define BATCH   4
#define NNODE   4096
#define DF      128
#define UNITS   128
#define TILE_R  128
#define SC      64                  // s-chunk rows per pipeline stage
#define NCHUNK  (NNODE / SC)        // 64
#define ADJ_STRIDE 132              // floats per adj smem row: 128 + 4 pad (528 B)
#define ADJ_ST_FLOATS (SC * ADJ_STRIDE)       // 8448 floats per adj stage
#define X_ST_FLOATS   (SC * DF)               // 8192 floats per x stage
#define XBASE         (3 * ADJ_ST_FLOATS)     // x stages start here (floats)

// Combined weights (device scratch; no cudaMalloc allowed)
//   g_Wap[p*256 + 2*c + e] = Wa[2p+e][c]   (pair p = k/2, e = k&1)
__device__ float g_Wap[DF * UNITS];  // W1 + Wr@W2, pair-interleaved
__device__ float g_Wbp[DF * UNITS];  // Ws@W2, pair-interleaved
__device__ float g_Wr2[DF * UNITS];  // Wr@W2 row-major (deg==0 fixup only)

// ---------------------------------------------------------------------------
// Phase 0: weight prep. 128 blocks x 128 threads. Block i computes row i.
// ---------------------------------------------------------------------------
__global__ void prep_weights(const float* __restrict__ Wmsg,
                             const float* __restrict__ Wupd) {
    __shared__ float ws[DF];
    __shared__ float wr[DF];
    const int i = blockIdx.x;
    const int j = threadIdx.x;
    ws[j] = Wmsg[i * UNITS + j];            // Ws[i][k]
    wr[j] = Wmsg[(DF + i) * UNITS + j];     // Wr[i][k]
    __syncthreads();
    float sa = 0.f, sr = 0.f;
#pragma unroll 4
    for (int k = 0; k < DF; ++k) {
        const float w2 = Wupd[(DF + k) * UNITS + j];   // W2[k][j]
        sa = fmaf(ws[k], w2, sa);
        sr = fmaf(wr[k], w2, sr);
    }
    const int pidx = (i >> 1) * 256 + (j << 1) + (i & 1);
    g_Wbp[pidx] = sa;                                   // Ws@W2
    g_Wr2[i * UNITS + j] = sr;
    g_Wap[pidx] = Wupd[i * UNITS + j] + sr;             // W1 + Wr@W2
}

// ---------------------------------------------------------------------------
// PTX helpers: bulk copy + mbarrier
// ---------------------------------------------------------------------------
__device__ __forceinline__ uint32_t smem_u32(const void* p) {
    uint32_t a;
    asm("{ .reg .u64 t; cvta.to.shared.u64 t, %1; cvt.u32.u64 %0, t; }"
        : "=r"(a) : "l"(p));
    return a;
}
__device__ __forceinline__ void mbar_init(uint32_t mbar, uint32_t cnt) {
    asm volatile("mbarrier.init.shared.b64 [%0], %1;" :: "r"(mbar), "r"(cnt) : "memory");
}
__device__ __forceinline__ void mbar_expect_tx(uint32_t mbar, uint32_t bytes) {
    asm volatile("mbarrier.arrive.expect_tx.shared.b64 _, [%0], %1;"
                 :: "r"(mbar), "r"(bytes) : "memory");
}
__device__ __forceinline__ void mbar_wait(uint32_t mbar, uint32_t parity) {
    uint32_t done;
    asm volatile(
        "{ .reg .pred p; mbarrier.try_wait.parity.acquire.cta.shared::cta.b64 p, [%1], %2;"
        " selp.b32 %0,1,0,p; }"
        : "=r"(done) : "r"(mbar), "r"(parity) : "memory");
    if (!done) {
        asm volatile(
            "{ .reg .pred P1;\n"
            "WL_%=: mbarrier.try_wait.parity.acquire.cta.shared::cta.b64 P1, [%0], %1, 0x989680;\n"
            "@P1 bra.uni WD_%=;\n"
            "bra.uni WL_%=;\n"
            "WD_%=: }"
            :: "r"(mbar), "r"(parity) : "memory");
    }
}
__device__ __forceinline__ void bulk_g2s(uint32_t dst, const void* src,
                                         uint32_t bytes, uint32_t mbar) {
    asm volatile(
        "cp.async.bulk.shared::cta.global.mbarrier::complete_tx::bytes [%0], [%1], %2, [%3];"
        :: "r"(dst), "l"(src), "r"(bytes), "r"(mbar) : "memory");
}

// Packed f32x2 FMA: d = a*b + d  (both lanes)
__device__ __forceinline__ void fma2(unsigned long long& d, unsigned long long a,
                                     unsigned long long b) {
    asm("fma.rn.f32x2 %0, %1, %2, %0;" : "+l"(d) : "l"(a), "l"(b));
}

// ---------------------------------------------------------------------------
// Main fused kernel
// grid = (32, 4), block = 1024 threads
// smem: 3 adj stages (64x132 f) + 3 x stages (64x128 f) = 199,680 B
// ---------------------------------------------------------------------------
extern __shared__ float smem[];

__global__ __launch_bounds__(1024, 1)
void mpnn_main(const float* __restrict__ x,
               const float* __restrict__ adj,
               float* __restrict__ out) {
    __shared__ __align__(8) unsigned long long mb[4];   // 3 stages + 1 for phase-2 x

    const int b   = blockIdx.y;
    const int r0  = blockIdx.x * TILE_R;
    const int tid = threadIdx.x;
    const int w    = tid >> 5;   // warp id: owns r-cols r0+4w .. 4w+3 in phase 1
    const int lane = tid & 31;

    const float* adjb = adj + (size_t)b * NNODE * NNODE;
    const float* xb   = x   + (size_t)b * NNODE * DF;

    const uint32_t mb_base = smem_u32(&mb[0]);
    if (tid == 0) {
        mbar_init(mb_base + 0,  128);
        mbar_init(mb_base + 8,  128);
        mbar_init(mb_base + 16, 128);
        mbar_init(mb_base + 24, 128);
    }
    __syncthreads();

    // one stage = adj chunk (64 rows x 512 B, threads 0..63)
    //           + x   chunk (64 rows x 512 B, threads 64..127); 64 KB total
    auto issue_chunk = [&](int c) {
        const int st = c % 3;
        if (tid < 128) {
            const uint32_t mbar = mb_base + st * 8;
            mbar_expect_tx(mbar, 512);
            if (tid < 64) {
                const uint32_t dst = smem_u32(
                    &smem[(size_t)st * ADJ_ST_FLOATS + (size_t)tid * ADJ_STRIDE]);
                bulk_g2s(dst, adjb + (size_t)(c * SC + tid) * NNODE + r0, 512, mbar);
            } else {
                const int row = tid - 64;
                const uint32_t dst = smem_u32(
                    &smem[XBASE + (size_t)st * X_ST_FLOATS + (size_t)row * DF]);
                bulk_g2s(dst, xb + (size_t)(c * SC + row) * DF, 512, mbar);
            }
        }
    };

    float acc[4][4] = {};
    float degf[4]   = {0.f, 0.f, 0.f, 0.f};

    // -------- phase 1: stream adj+x (3-stage bulk), scan & aggregate from SMEM ----
    issue_chunk(0);
    issue_chunk(1);
    issue_chunk(2);

    for (int c = 0; c < NCHUNK; ++c) {
        const int st = c % 3;
        mbar_wait(mb_base + st * 8, (c / 3) & 1);

        const float* cur_a = smem + (size_t)st * ADJ_ST_FLOATS;
        const float* cur_x = smem + XBASE + (size_t)st * X_ST_FLOATS;

#pragma unroll
        for (int sb = 0; sb < SC; sb += 32) {
            const float4 av = *reinterpret_cast<const float4*>(
                &cur_a[(sb + lane) * ADJ_STRIDE + (w << 2)]);
            // exact per-lane partial degree (entries are exactly 0.0 / 1.0)
            degf[0] += av.x; degf[1] += av.y; degf[2] += av.z; degf[3] += av.w;
            const float s = (av.x + av.y) + (av.z + av.w);
            unsigned m = __ballot_sync(0xffffffffu, s != 0.0f);
            while (m) {
                const int i = __ffs(m) - 1; m &= m - 1;
                const float4 a2 = *reinterpret_cast<const float4*>(
                    &cur_a[(sb + i) * ADJ_STRIDE + (w << 2)]);
                const float4 xv = *reinterpret_cast<const float4*>(
                    &cur_x[(sb + i) * DF + (lane << 2)]);   // SMEM, 29-cyc latency
                acc[0][0] = fmaf(a2.x, xv.x, acc[0][0]);
                acc[0][1] = fmaf(a2.x, xv.y, acc[0][1]);
                acc[0][2] = fmaf(a2.x, xv.z, acc[0][2]);
                acc[0][3] = fmaf(a2.x, xv.w, acc[0][3]);
                acc[1][0] = fmaf(a2.y, xv.x, acc[1][0]);
                acc[1][1] = fmaf(a2.y, xv.y, acc[1][1]);
                acc[1][2] = fmaf(a2.y, xv.z, acc[1][2]);
                acc[1][3] = fmaf(a2.y, xv.w, acc[1][3]);
                acc[2][0] = fmaf(a2.z, xv.x, acc[2][0]);
                acc[2][1] = fmaf(a2.z, xv.y, acc[2][1]);
                acc[2][2] = fmaf(a2.z, xv.z, acc[2][2]);
                acc[2][3] = fmaf(a2.z, xv.w, acc[2][3]);
                acc[3][0] = fmaf(a2.w, xv.x, acc[3][0]);
                acc[3][1] = fmaf(a2.w, xv.y, acc[3][1]);
                acc[3][2] = fmaf(a2.w, xv.z, acc[3][2]);
                acc[3][3] = fmaf(a2.w, xv.w, acc[3][3]);
            }
        }
        __syncthreads();              // all readers of stage st done before refill
        if (c + 3 < NCHUNK) issue_chunk(c + 3);
    }

    // warp-reduce partial degrees (each lane held the s = lane slice sums)
#pragma unroll
    for (int rp = 0; rp < 4; ++rp) {
#pragma unroll
        for (int off = 16; off; off >>= 1)
            degf[rp] += __shfl_xor_sync(0xffffffffu, degf[rp], off);
    }

    // -------- phase boundary: overlay smem with xsm / zsm / degs --------
    float* xsm  = smem;                       // [128][128]
    float* zsm  = smem + TILE_R * DF;         // [128][128]
    float* degs = smem + 2 * TILE_R * DF;     // [128]

    // stage this block's own x rows (contiguous 512 B per row) via bulk copy
    if (tid < 128) {
        mbar_expect_tx(mb_base + 24, 512);
        bulk_g2s(smem_u32(&xsm[(size_t)tid * DF]),
                 xb + (size_t)(r0 + tid) * DF, 512, mb_base + 24);
    }

#pragma unroll
    for (int rp = 0; rp < 4; ++rp) {
        const int r = (w << 2) + rp;
        const float d = degf[rp];
        const float inv = (d > 0.0f) ? (1.0f / d) : 0.0f;
        float4 zv;
        zv.x = acc[rp][0] * inv; zv.y = acc[rp][1] * inv;
        zv.z = acc[rp][2] * inv; zv.w = acc[rp][3] * inv;
        *reinterpret_cast<float4*>(&zsm[r * DF + (lane << 2)]) = zv;
        if (lane == 0) degs[r] = d;
    }

    mbar_wait(mb_base + 24, 0);
    __syncthreads();

    // -------- phase 2: out = xsm @ Wa + zsm @ Wb  (k-pair packed f32x2) --------
    // warp tile: 16 rows x 32 cols; lane owns 1 col, 16 rows.
    const int rg  = w >> 2;                 // 0..7 -> rows 16*rg .. +16
    const int col = ((w & 3) << 5) + lane;  // 0..127

    unsigned long long cacc[16];
#pragma unroll
    for (int i = 0; i < 16; ++i) cacc[i] = 0ull;

#pragma unroll 1
    for (int pass = 0; pass < 2; ++pass) {
        const float* A  = pass ? zsm : xsm;
        const float* Wp = pass ? g_Wbp : g_Wap;
#pragma unroll 4
        for (int k = 0; k < DF; k += 4) {   // 2 k-pairs per step
            const unsigned long long w0 = *reinterpret_cast<const unsigned long long*>(
                &Wp[(size_t)(k >> 1) * 256 + (col << 1)]);
            const unsigned long long w1 = *reinterpret_cast<const unsigned long long*>(
                &Wp[(size_t)((k >> 1) + 1) * 256 + (col << 1)]);
#pragma unroll
            for (int i = 0; i < 16; ++i) {
                const ulonglong2 av = *reinterpret_cast<const ulonglong2*>(
                    &A[(16 * rg + i) * DF + k]);      // warp-uniform (broadcast LDS)
                fma2(cacc[i], av.x, w0);
                fma2(cacc[i], av.y, w1);
            }
        }
    }

    float* outb = out + ((size_t)b * NNODE + r0) * UNITS;
#pragma unroll
    for (int i = 0; i < 16; ++i) {
        const int r = 16 * rg + i;
        unsigned lo, hi;
        asm("mov.b64 {%0, %1}, %2;" : "=r"(lo), "=r"(hi) : "l"(cacc[i]));
        float o = __uint_as_float(lo) + __uint_as_float(hi);

        if (degs[r] == 0.0f) {
            // message term must be exactly zero: remove the x@Wr@W2 contribution
            float corr = 0.0f;
            for (int k = 0; k < DF; ++k)
                corr = fmaf(xsm[r * DF + k], g_Wr2[k * UNITS + col], corr);
            o -= corr;
        }
        outb[(size_t)r * UNITS + col] = o;
    }
}

// ---------------------------------------------------------------------------
// Launch
// ---------------------------------------------------------------------------
extern "C" void kernel_launch(void* const* d_in, const int* in_sizes, int n_in,
                              void* d_out, int out_size) {
    (void)in_sizes; (void)n_in; (void)out_size;
    const float* x    = (const float*)d_in[0];
    const float* adj  = (const float*)d_in[1];
    const float* Wmsg = (const float*)d_in[2];
    const float* Wupd = (const float*)d_in[3];
    float* out = (float*)d_out;

    prep_weights<<<128, 128>>>(Wmsg, Wupd);

    const size_t shbytes = (size_t)(3 * ADJ_ST_FLOATS + 3 * X_ST_FLOATS) * sizeof(float);
    cudaFuncSetAttribute(mpnn_main, cudaFuncAttributeMaxDynamicSharedMemorySize,
                         (int)shbytes);
    mpnn_main<<<dim3(32, 4), 1024, shbytes>>>(x, adj, out);
}

// round 8
// speedup vs baseline: 1.0781x; 1.0781x over previous
#include <cuda_runtime.h>
#include <cstdint>
#include <cstddef>

#define BATCH   4
#define NNODE   4096
#define DF      128
#define UNITS   128
#define TILE_R  128
#define SC      128                 // s-chunk rows per pipeline stage
#define NCHUNK  (NNODE / SC)        // 32
#define ADJ_STRIDE 132              // floats per adj smem row: 128 + 4 pad (528 B)
#define ADJ_ST_FLOATS (SC * ADJ_STRIDE)

// Combined weights (device scratch; no cudaMalloc allowed)
//   g_Wap[p*256 + 2*c + e] = Wa[2p+e][c]   (pair p = k/2, e = k&1)
__device__ float g_Wap[DF * UNITS];  // W1 + Wr@W2, pair-interleaved
__device__ float g_Wbp[DF * UNITS];  // Ws@W2, pair-interleaved
__device__ float g_Wr2[DF * UNITS];  // Wr@W2 row-major (deg==0 fixup only)

// ---------------------------------------------------------------------------
// Phase 0: weight prep. 128 blocks x 128 threads. Block i computes row i.
// ---------------------------------------------------------------------------
__global__ void prep_weights(const float* __restrict__ Wmsg,
                             const float* __restrict__ Wupd) {
    __shared__ float ws[DF];
    __shared__ float wr[DF];
    const int i = blockIdx.x;
    const int j = threadIdx.x;
    ws[j] = Wmsg[i * UNITS + j];            // Ws[i][k]
    wr[j] = Wmsg[(DF + i) * UNITS + j];     // Wr[i][k]
    __syncthreads();
    float sa = 0.f, sr = 0.f;
#pragma unroll 4
    for (int k = 0; k < DF; ++k) {
        const float w2 = Wupd[(DF + k) * UNITS + j];   // W2[k][j]
        sa = fmaf(ws[k], w2, sa);
        sr = fmaf(wr[k], w2, sr);
    }
    const int pidx = (i >> 1) * 256 + (j << 1) + (i & 1);
    g_Wbp[pidx] = sa;                                   // Ws@W2
    g_Wr2[i * UNITS + j] = sr;
    g_Wap[pidx] = Wupd[i * UNITS + j] + sr;             // W1 + Wr@W2
}

// ---------------------------------------------------------------------------
// PTX helpers: bulk copy + mbarrier
// ---------------------------------------------------------------------------
__device__ __forceinline__ uint32_t smem_u32(const void* p) {
    uint32_t a;
    asm("{ .reg .u64 t; cvta.to.shared.u64 t, %1; cvt.u32.u64 %0, t; }"
        : "=r"(a) : "l"(p));
    return a;
}
__device__ __forceinline__ void mbar_init(uint32_t mbar, uint32_t cnt) {
    asm volatile("mbarrier.init.shared.b64 [%0], %1;" :: "r"(mbar), "r"(cnt) : "memory");
}
__device__ __forceinline__ void mbar_expect_tx(uint32_t mbar, uint32_t bytes) {
    asm volatile("mbarrier.arrive.expect_tx.shared.b64 _, [%0], %1;"
                 :: "r"(mbar), "r"(bytes) : "memory");
}
__device__ __forceinline__ void mbar_wait(uint32_t mbar, uint32_t parity) {
    uint32_t done;
    asm volatile(
        "{ .reg .pred p; mbarrier.try_wait.parity.acquire.cta.shared::cta.b64 p, [%1], %2;"
        " selp.b32 %0,1,0,p; }"
        : "=r"(done) : "r"(mbar), "r"(parity) : "memory");
    if (!done) {
        asm volatile(
            "{ .reg .pred P1;\n"
            "WL_%=: mbarrier.try_wait.parity.acquire.cta.shared::cta.b64 P1, [%0], %1, 0x989680;\n"
            "@P1 bra.uni WD_%=;\n"
            "bra.uni WL_%=;\n"
            "WD_%=: }"
            :: "r"(mbar), "r"(parity) : "memory");
    }
}
__device__ __forceinline__ void bulk_g2s(uint32_t dst, const void* src,
                                         uint32_t bytes, uint32_t mbar) {
    asm volatile(
        "cp.async.bulk.shared::cta.global.mbarrier::complete_tx::bytes [%0], [%1], %2, [%3];"
        :: "r"(dst), "l"(src), "r"(bytes), "r"(mbar) : "memory");
}

// Packed f32x2 FMA: d = a*b + d  (both lanes)
__device__ __forceinline__ void fma2(unsigned long long& d, unsigned long long a,
                                     unsigned long long b) {
    asm("fma.rn.f32x2 %0, %1, %2, %0;" : "+l"(d) : "l"(a), "l"(b));
}

// ---------------------------------------------------------------------------
// Main fused kernel
// grid = (32, 4), block = 1024 threads, smem = 3 * SC * ADJ_STRIDE * 4 B
// ---------------------------------------------------------------------------
extern __shared__ float smem[];

__global__ __launch_bounds__(1024, 1)
void mpnn_main(const float* __restrict__ x,
               const float* __restrict__ adj,
               float* __restrict__ out) {
    __shared__ __align__(8) unsigned long long mb[4];   // 3 adj stages + 1 for x

    const int b   = blockIdx.y;
    const int r0  = blockIdx.x * TILE_R;
    const int tid = threadIdx.x;
    const int w    = tid >> 5;   // warp id: owns r-cols r0+4w .. 4w+3 in phase 1
    const int lane = tid & 31;

    const float* adjb = adj + (size_t)b * NNODE * NNODE;
    const float* xb   = x   + (size_t)b * NNODE * DF;

    const uint32_t mb_base = smem_u32(&mb[0]);
    if (tid == 0) {
        mbar_init(mb_base + 0,  128);
        mbar_init(mb_base + 8,  128);
        mbar_init(mb_base + 16, 128);
        mbar_init(mb_base + 24, 128);
    }
    __syncthreads();

    // issue one adj chunk: 128 row copies of 512 B (threads 0..127)
    auto issue_chunk = [&](int c) {
        const int st = c % 3;
        if (tid < 128) {
            const uint32_t mbar = mb_base + st * 8;
            mbar_expect_tx(mbar, 512);                 // 128 x 512 = 64 KB total
            const uint32_t dst = smem_u32(
                &smem[(size_t)st * ADJ_ST_FLOATS + (size_t)tid * ADJ_STRIDE]);
            bulk_g2s(dst, adjb + (size_t)(c * SC + tid) * NNODE + r0, 512, mbar);
        }
    };

    float acc[4][4] = {};
    int   dcnt[4]   = {0, 0, 0, 0};

    // -------- phase 1: stream adj via cp.async.bulk (3-stage), per-r scan ----------
    issue_chunk(0);
    issue_chunk(1);
    issue_chunk(2);

    for (int c = 0; c < NCHUNK; ++c) {
        const int st = c % 3;
        mbar_wait(mb_base + st * 8, (c / 3) & 1);

        const float* cur = smem + (size_t)st * ADJ_ST_FLOATS;
        const int s_chunk = c << 7;   // c * SC

#pragma unroll
        for (int sb = 0; sb < SC; sb += 32) {
            const float4 av = *reinterpret_cast<const float4*>(
                &cur[(sb + lane) * ADJ_STRIDE + (w << 2)]);
            const int s_base = s_chunk + sb;

            // per-r-column ballots: a set bit means adj value is EXACTLY 1.0,
            // so the aggregate is a plain add of x[s] — no multiply, no re-read.
            unsigned m0 = __ballot_sync(0xffffffffu, av.x != 0.0f);
            unsigned m1 = __ballot_sync(0xffffffffu, av.y != 0.0f);
            unsigned m2 = __ballot_sync(0xffffffffu, av.z != 0.0f);
            unsigned m3 = __ballot_sync(0xffffffffu, av.w != 0.0f);
            dcnt[0] += __popc(m0);
            dcnt[1] += __popc(m1);
            dcnt[2] += __popc(m2);
            dcnt[3] += __popc(m3);

#define SCAN_COMP(MASK, RP)                                                          \
            while (MASK) {                                                           \
                const int i = __ffs(MASK) - 1; MASK &= MASK - 1;                     \
                const float4 xv = *reinterpret_cast<const float4*>(                  \
                    &xb[(size_t)(s_base + i) * DF + (lane << 2)]);                   \
                acc[RP][0] += xv.x; acc[RP][1] += xv.y;                              \
                acc[RP][2] += xv.z; acc[RP][3] += xv.w;                              \
            }
            SCAN_COMP(m0, 0)
            SCAN_COMP(m1, 1)
            SCAN_COMP(m2, 2)
            SCAN_COMP(m3, 3)
#undef SCAN_COMP
        }
        __syncthreads();              // all readers of stage st done before refill
        if (c + 3 < NCHUNK) issue_chunk(c + 3);
    }

    // -------- phase boundary: overlay smem with xsm / zsm / degs --------
    float* xsm  = smem;                       // [128][128]
    float* zsm  = smem + TILE_R * DF;         // [128][128]
    float* degs = smem + 2 * TILE_R * DF;     // [128]

    // stage this block's own x rows (contiguous 512 B per row) via bulk copy
    if (tid < 128) {
        mbar_expect_tx(mb_base + 24, 512);
        bulk_g2s(smem_u32(&xsm[(size_t)tid * DF]),
                 xb + (size_t)(r0 + tid) * DF, 512, mb_base + 24);
    }

    // dcnt is warp-uniform (popc of full ballots) -> no reduction needed
#pragma unroll
    for (int rp = 0; rp < 4; ++rp) {
        const int r = (w << 2) + rp;
        const float d = (float)dcnt[rp];
        const float inv = (dcnt[rp] > 0) ? (1.0f / d) : 0.0f;
        float4 zv;
        zv.x = acc[rp][0] * inv; zv.y = acc[rp][1] * inv;
        zv.z = acc[rp][2] * inv; zv.w = acc[rp][3] * inv;
        *reinterpret_cast<float4*>(&zsm[r * DF + (lane << 2)]) = zv;
        if (lane == 0) degs[r] = d;
    }

    mbar_wait(mb_base + 24, 0);
    __syncthreads();

    // -------- phase 2: out = xsm @ Wa + zsm @ Wb  (k-pair packed f32x2) --------
    // warp tile: 16 rows x 32 cols; lane owns 1 col, 16 rows.
    const int rg  = w >> 2;                 // 0..7 -> rows 16*rg .. +16
    const int col = ((w & 3) << 5) + lane;  // 0..127

    unsigned long long cacc[16];
#pragma unroll
    for (int i = 0; i < 16; ++i) cacc[i] = 0ull;

#pragma unroll 1
    for (int pass = 0; pass < 2; ++pass) {
        const float* A  = pass ? zsm : xsm;
        const float* Wp = pass ? g_Wbp : g_Wap;
#pragma unroll 4
        for (int k = 0; k < DF; k += 4) {   // 2 k-pairs per step
            const unsigned long long w0 = *reinterpret_cast<const unsigned long long*>(
                &Wp[(size_t)(k >> 1) * 256 + (col << 1)]);
            const unsigned long long w1 = *reinterpret_cast<const unsigned long long*>(
                &Wp[(size_t)((k >> 1) + 1) * 256 + (col << 1)]);
#pragma unroll
            for (int i = 0; i < 16; ++i) {
                const ulonglong2 av = *reinterpret_cast<const ulonglong2*>(
                    &A[(16 * rg + i) * DF + k]);      // warp-uniform (broadcast LDS)
                fma2(cacc[i], av.x, w0);
                fma2(cacc[i], av.y, w1);
            }
        }
    }

    float* outb = out + ((size_t)b * NNODE + r0) * UNITS;
#pragma unroll
    for (int i = 0; i < 16; ++i) {
        const int r = 16 * rg + i;
        unsigned lo, hi;
        asm("mov.b64 {%0, %1}, %2;" : "=r"(lo), "=r"(hi) : "l"(cacc[i]));
        float o = __uint_as_float(lo) + __uint_as_float(hi);

        if (degs[r] == 0.0f) {
            // message term must be exactly zero: remove the x@Wr@W2 contribution
            float corr = 0.0f;
            for (int k = 0; k < DF; ++k)
                corr = fmaf(xsm[r * DF + k], g_Wr2[k * UNITS + col], corr);
            o -= corr;
        }
        outb[(size_t)r * UNITS + col] = o;
    }
}

// ---------------------------------------------------------------------------
// Launch
// ---------------------------------------------------------------------------
extern "C" void kernel_launch(void* const* d_in, const int* in_sizes, int n_in,
                              void* d_out, int out_size) {
    (void)in_sizes; (void)n_in; (void)out_size;
    const float* x    = (const float*)d_in[0];
    const float* adj  = (const float*)d_in[1];
    const float* Wmsg = (const float*)d_in[2];
    const float* Wupd = (const float*)d_in[3];
    float* out = (float*)d_out;

    prep_weights<<<128, 128>>>(Wmsg, Wupd);

    const size_t shbytes = (size_t)3 * ADJ_ST_FLOATS * sizeof(float);  // 202752
    cudaFuncSetAttribute(mpnn_main, cudaFuncAttributeMaxDynamicSharedMemorySize,
                         (int)shbytes);
    mpnn_main<<<dim3(32, 4), 1024, shbytes>>>(x, adj, out);
}

// round 11
// speedup vs baseline: 1.1059x; 1.0258x over previous
#include <cuda_runtime.h>
#include <cstdint>
#include <cstddef>

#define BATCH   4
#define NNODE   4096
#define DF      128
#define UNITS   128
#define TILE_R  64                  // r columns per block (2 blocks/SM)
#define SC      128                 // s-chunk rows per pipeline stage
#define NCHUNK  (NNODE / SC)        // 32
#define ADJ_STRIDE 68               // floats per adj smem row: 64 + 4 pad (272 B)
#define ADJ_ST_FLOATS (SC * ADJ_STRIDE)   // 8704 floats / stage
#define ZS      132                 // zsm row stride (floats)

// Combined weights (device scratch; no cudaMalloc allowed)
//   g_Wap[p*256 + 2*c + e] = Wa[2p+e][c]   (pair p = k/2, e = k&1)
__device__ float g_Wap[DF * UNITS];  // W1 + Wr@W2, pair-interleaved
__device__ float g_Wbp[DF * UNITS];  // Ws@W2, pair-interleaved
__device__ float g_Wr2[DF * UNITS];  // Wr@W2 row-major (deg==0 fixup only)

// ---------------------------------------------------------------------------
// Phase 0: weight prep. 128 blocks x 128 threads. Block i computes row i.
// ---------------------------------------------------------------------------
__global__ void prep_weights(const float* __restrict__ Wmsg,
                             const float* __restrict__ Wupd) {
    __shared__ float ws[DF];
    __shared__ float wr[DF];
    const int i = blockIdx.x;
    const int j = threadIdx.x;
    ws[j] = Wmsg[i * UNITS + j];            // Ws[i][k]
    wr[j] = Wmsg[(DF + i) * UNITS + j];     // Wr[i][k]
    __syncthreads();
    float sa = 0.f, sr = 0.f;
#pragma unroll 4
    for (int k = 0; k < DF; ++k) {
        const float w2 = Wupd[(DF + k) * UNITS + j];   // W2[k][j]
        sa = fmaf(ws[k], w2, sa);
        sr = fmaf(wr[k], w2, sr);
    }
    const int pidx = (i >> 1) * 256 + (j << 1) + (i & 1);
    g_Wbp[pidx] = sa;                                   // Ws@W2
    g_Wr2[i * UNITS + j] = sr;
    g_Wap[pidx] = Wupd[i * UNITS + j] + sr;             // W1 + Wr@W2
}

// ---------------------------------------------------------------------------
// PTX helpers: bulk copy + mbarrier
// ---------------------------------------------------------------------------
__device__ __forceinline__ uint32_t smem_u32(const void* p) {
    uint32_t a;
    asm("{ .reg .u64 t; cvta.to.shared.u64 t, %1; cvt.u32.u64 %0, t; }"
        : "=r"(a) : "l"(p));
    return a;
}
__device__ __forceinline__ void mbar_init(uint32_t mbar, uint32_t cnt) {
    asm volatile("mbarrier.init.shared.b64 [%0], %1;" :: "r"(mbar), "r"(cnt) : "memory");
}
__device__ __forceinline__ void mbar_expect_tx(uint32_t mbar, uint32_t bytes) {
    asm volatile("mbarrier.arrive.expect_tx.shared.b64 _, [%0], %1;"
                 :: "r"(mbar), "r"(bytes) : "memory");
}
__device__ __forceinline__ void mbar_wait(uint32_t mbar, uint32_t parity) {
    uint32_t done;
    asm volatile(
        "{ .reg .pred p; mbarrier.try_wait.parity.acquire.cta.shared::cta.b64 p, [%1], %2;"
        " selp.b32 %0,1,0,p; }"
        : "=r"(done) : "r"(mbar), "r"(parity) : "memory");
    if (!done) {
        asm volatile(
            "{ .reg .pred P1;\n"
            "WL_%=: mbarrier.try_wait.parity.acquire.cta.shared::cta.b64 P1, [%0], %1, 0x989680;\n"
            "@P1 bra.uni WD_%=;\n"
            "bra.uni WL_%=;\n"
            "WD_%=: }"
            :: "r"(mbar), "r"(parity) : "memory");
    }
}
__device__ __forceinline__ void bulk_g2s(uint32_t dst, const void* src,
                                         uint32_t bytes, uint32_t mbar) {
    asm volatile(
        "cp.async.bulk.shared::cta.global.mbarrier::complete_tx::bytes [%0], [%1], %2, [%3];"
        :: "r"(dst), "l"(src), "r"(bytes), "r"(mbar) : "memory");
}

// Packed f32x2 FMA: d = a*b + d  (both lanes)
__device__ __forceinline__ void fma2(unsigned long long& d, unsigned long long a,
                                     unsigned long long b) {
    asm("fma.rn.f32x2 %0, %1, %2, %0;" : "+l"(d) : "l"(a), "l"(b));
}

// ---------------------------------------------------------------------------
// Main fused kernel
// grid = (64, 4), block = 512 threads, 2 blocks/SM
// smem = 3 * SC * ADJ_STRIDE * 4 = 104448 B per block
// ---------------------------------------------------------------------------
extern __shared__ float smem[];

__global__ __launch_bounds__(512, 2)
void mpnn_main(const float* __restrict__ x,
               const float* __restrict__ adj,
               float* __restrict__ out) {
    __shared__ __align__(8) unsigned long long mb[4];   // 3 adj stages + 1 for x
    __shared__ float degs[TILE_R];

    const int b   = blockIdx.y;
    const int r0  = blockIdx.x * TILE_R;
    const int tid = threadIdx.x;
    const int w    = tid >> 5;   // warp 0..15: owns r-cols r0+4w .. 4w+3
    const int lane = tid & 31;

    const float* adjb = adj + (size_t)b * NNODE * NNODE;
    const float* xb   = x   + (size_t)b * NNODE * DF;

    const uint32_t mb_base = smem_u32(&mb[0]);
    if (tid == 0) {
        mbar_init(mb_base + 0,  128);
        mbar_init(mb_base + 8,  128);
        mbar_init(mb_base + 16, 128);
        mbar_init(mb_base + 24, 64);
    }
    __syncthreads();

    // issue one adj chunk: 128 row copies of 256 B (threads 0..127)
    auto issue_chunk = [&](int c) {
        const int st = c % 3;
        if (tid < 128) {
            const uint32_t mbar = mb_base + st * 8;
            mbar_expect_tx(mbar, 256);                 // 128 x 256 = 32 KB total
            const uint32_t dst = smem_u32(
                &smem[(size_t)st * ADJ_ST_FLOATS + (size_t)tid * ADJ_STRIDE]);
            bulk_g2s(dst, adjb + (size_t)(c * SC + tid) * NNODE + r0, 256, mbar);
        }
    };

    float acc[4][4] = {};
    int   dcnt[4]   = {0, 0, 0, 0};

    // -------- phase 1: stream adj via cp.async.bulk (3-stage), per-r scan ----------
    issue_chunk(0);
    issue_chunk(1);
    issue_chunk(2);

    for (int c = 0; c < NCHUNK; ++c) {
        const int st = c % 3;
        mbar_wait(mb_base + st * 8, (c / 3) & 1);

        const float* cur = smem + (size_t)st * ADJ_ST_FLOATS;
        const int s_chunk = c << 7;   // c * SC

#pragma unroll
        for (int sb = 0; sb < SC; sb += 32) {
            const float4 av = *reinterpret_cast<const float4*>(
                &cur[(sb + lane) * ADJ_STRIDE + (w << 2)]);
            const int s_base = s_chunk + sb;

            // per-r-column ballots: a set bit means adj value is EXACTLY 1.0,
            // so the aggregate is a plain add of x[s] — no multiply, no re-read.
            unsigned m0 = __ballot_sync(0xffffffffu, av.x != 0.0f);
            unsigned m1 = __ballot_sync(0xffffffffu, av.y != 0.0f);
            unsigned m2 = __ballot_sync(0xffffffffu, av.z != 0.0f);
            unsigned m3 = __ballot_sync(0xffffffffu, av.w != 0.0f);
            dcnt[0] += __popc(m0);
            dcnt[1] += __popc(m1);
            dcnt[2] += __popc(m2);
            dcnt[3] += __popc(m3);

#define SCAN_COMP(MASK, RP)                                                          \
            while (MASK) {                                                           \
                const int i = __ffs(MASK) - 1; MASK &= MASK - 1;                     \
                const float4 xv = *reinterpret_cast<const float4*>(                  \
                    &xb[(size_t)(s_base + i) * DF + (lane << 2)]);                   \
                acc[RP][0] += xv.x; acc[RP][1] += xv.y;                              \
                acc[RP][2] += xv.z; acc[RP][3] += xv.w;                              \
            }
            SCAN_COMP(m0, 0)
            SCAN_COMP(m1, 1)
            SCAN_COMP(m2, 2)
            SCAN_COMP(m3, 3)
#undef SCAN_COMP
        }
        __syncthreads();              // all readers of stage st done before refill
        if (c + 3 < NCHUNK) issue_chunk(c + 3);
    }

    // -------- phase boundary: overlay smem with zsm / xsm --------
    float* zsm = smem;                         // [64][ZS]
    float* xsm = smem + TILE_R * ZS;           // [64][128], offset 8448 floats

    // stage this block's own x rows (contiguous 512 B per row) via bulk copy
    if (tid < TILE_R) {
        mbar_expect_tx(mb_base + 24, 512);
        bulk_g2s(smem_u32(&xsm[(size_t)tid * DF]),
                 xb + (size_t)(r0 + tid) * DF, 512, mb_base + 24);
    }

    // dcnt is warp-uniform (popc of full ballots) -> no reduction needed
#pragma unroll
    for (int rp = 0; rp < 4; ++rp) {
        const int r = (w << 2) + rp;
        const float d = (float)dcnt[rp];
        const float inv = (dcnt[rp] > 0) ? (1.0f / d) : 0.0f;
        float4 zv;
        zv.x = acc[rp][0] * inv; zv.y = acc[rp][1] * inv;
        zv.z = acc[rp][2] * inv; zv.w = acc[rp][3] * inv;
        *reinterpret_cast<float4*>(&zsm[(size_t)r * ZS + (lane << 2)]) = zv;
        if (lane == 0) degs[r] = d;
    }

    mbar_wait(mb_base + 24, 0);
    __syncthreads();

    // -------- phase 2: out = xsm @ Wa + zsm @ Wb  (k-pair packed f32x2) --------
    // warp tile: 16 rows x 32 cols; lane owns 1 col, 16 rows.
    const int rg  = w >> 2;                 // 0..3 -> rows 16*rg .. +16
    const int col = ((w & 3) << 5) + lane;  // 0..127

    unsigned long long cacc[16];
#pragma unroll
    for (int i = 0; i < 16; ++i) cacc[i] = 0ull;

#pragma unroll 1
    for (int pass = 0; pass < 2; ++pass) {
        const float* A  = pass ? zsm : xsm;
        const int    As = pass ? ZS : DF;
        const float* Wp = pass ? g_Wbp : g_Wap;
#pragma unroll 4
        for (int k = 0; k < DF; k += 4) {   // 2 k-pairs per step
            const unsigned long long w0 = *reinterpret_cast<const unsigned long long*>(
                &Wp[(size_t)(k >> 1) * 256 + (col << 1)]);
            const unsigned long long w1 = *reinterpret_cast<const unsigned long long*>(
                &Wp[(size_t)((k >> 1) + 1) * 256 + (col << 1)]);
#pragma unroll
            for (int i = 0; i < 16; ++i) {
                const ulonglong2 av = *reinterpret_cast<const ulonglong2*>(
                    &A[(size_t)(16 * rg + i) * As + k]);   // warp-uniform broadcast
                fma2(cacc[i], av.x, w0);
                fma2(cacc[i], av.y, w1);
            }
        }
    }

    float* outb = out + ((size_t)b * NNODE + r0) * UNITS;
#pragma unroll
    for (int i = 0; i < 16; ++i) {
        const int r = 16 * rg + i;
        unsigned lo, hi;
        asm("mov.b64 {%0, %1}, %2;" : "=r"(lo), "=r"(hi) : "l"(cacc[i]));
        float o = __uint_as_float(lo) + __uint_as_float(hi);

        if (degs[r] == 0.0f) {
            // message term must be exactly zero: remove the x@Wr@W2 contribution
            float corr = 0.0f;
            for (int k = 0; k < DF; ++k)
                corr = fmaf(xsm[(size_t)r * DF + k], g_Wr2[k * UNITS + col], corr);
            o -= corr;
        }
        outb[(size_t)r * UNITS + col] = o;
    }
}

// ---------------------------------------------------------------------------
// Launch
// ---------------------------------------------------------------------------
extern "C" void kernel_launch(void* const* d_in, const int* in_sizes, int n_in,
                              void* d_out, int out_size) {
    (void)in_sizes; (void)n_in; (void)out_size;
    const float* x    = (const float*)d_in[0];
    const float* adj  = (const float*)d_in[1];
    const float* Wmsg = (const float*)d_in[2];
    const float* Wupd = (const float*)d_in[3];
    float* out = (float*)d_out;

    prep_weights<<<128, 128>>>(Wmsg, Wupd);

    const size_t shbytes = (size_t)3 * ADJ_ST_FLOATS * sizeof(float);  // 104448
    cudaFuncSetAttribute(mpnn_main, cudaFuncAttributeMaxDynamicSharedMemorySize,
                         (int)shbytes);
    mpnn_main<<<dim3(NNODE / TILE_R, BATCH), 512, shbytes>>>(x, adj, out);
}